// round 1
// baseline (speedup 1.0000x reference)
#include <cuda_runtime.h>

// LSTM_10960756539796: B=256, T=512, D=64, H=256, C=10
//
// Persistent kernel, 128 CTAs x 256 threads.
//   group g = blockIdx/8  -> batch rows [g*16, g*16+16)
//   rank  r = blockIdx%8  -> hidden units [r*32, r*32+32)
//                            = W_hh gate rows {gate*256 + r*32 + u}
// W_hh slice (128 rows x 256) lives in registers (128 floats/thread,
// 2-way k-split across the 256 threads). Per step only h (16x256) is
// exchanged through L2 with per-(group,step) arrival counters and a
// parity-double-buffered h store.

#define BATCH 256
#define TT    512
#define DD    64
#define HH    256
#define NGRP  16   // batch groups
#define NRNK  8    // CTAs per group (hidden split)
#define BB    16   // batch rows per group
#define HU    32   // hidden units per rank
#define NL    128  // gate rows per rank (4*HU)

// scratch (static __device__ globals: allowed; no allocation)
__device__ float g_H[2][BATCH][HH];    // [parity][b][k]
__device__ int   g_cnt[NGRP][TT];      // arrival counters, zero-init
__device__ int   g_done[NGRP];         // end-of-kernel barrier for reset

__device__ __forceinline__ int   vloadi(const int* p)   { return *(const volatile int*)p; }
__device__ __forceinline__ float vloadf(const float* p) { return *(const volatile float*)p; }

__global__ __launch_bounds__(256, 1)
void lstm_persistent_kernel(const float* __restrict__ x,
                            const float* __restrict__ W_ih,
                            const float* __restrict__ W_hh,
                            const float* __restrict__ b_ih,
                            const float* __restrict__ b_hh,
                            const float* __restrict__ W_out,
                            const float* __restrict__ b_out,
                            float* __restrict__ out)
{
    const int g   = blockIdx.x / NRNK;
    const int r   = blockIdx.x % NRNK;
    const int tid = threadIdx.x;
    const int n   = tid & 127;   // local gate row 0..127 (= gate*32 + u)
    const int kh  = tid >> 7;    // k-half: 0 -> k[0,128)+d[0,32), 1 -> k[128,256)+d[32,64)

    __shared__ __align__(16) float h_sm[BB][HH];     // 16 KB
    __shared__ __align__(16) float x_sm[BB][DD];     //  4 KB
    __shared__ __align__(16) float zp[2][BB][NL];    // 16 KB (k-split partials)
    __shared__ float c_sm[BB * HU];                  //  2 KB

    const int gate  = n >> 5;
    const int u     = n & 31;
    const int nglob = gate * HH + r * HU + u;        // global W row (torch gate order i,f,g,o)

    // ---- load weights into registers (resident for the whole kernel) ----
    float Wr[128];
    #pragma unroll
    for (int i = 0; i < 128; i++) Wr[i] = W_hh[nglob * HH + kh * 128 + i];
    float Wi[32];
    #pragma unroll
    for (int i = 0; i < 32; i++)  Wi[i] = W_ih[nglob * DD + kh * 32 + i];
    const float bias = (kh == 0) ? (b_ih[nglob] + b_hh[nglob]) : 0.0f;

    // ---- init state: h0 = c0 = 0 ----
    for (int i = tid; i < BB * HH; i += 256) (&h_sm[0][0])[i] = 0.0f;
    for (int i = tid; i < BB * HU; i += 256) c_sm[i] = 0.0f;
    __syncthreads();

    const float* xbase = x + (size_t)(g * BB) * TT * DD;

    #pragma unroll 1
    for (int t = 0; t < TT; t++) {
        // load x_t tile for this group's batch rows
        for (int i = tid; i < BB * DD; i += 256) {
            int b = i >> 6, d = i & 63;
            x_sm[b][d] = xbase[((size_t)b * TT + t) * DD + d];
        }
        if (t > 0) {
            // wait for all 8 ranks' h_{t} slices (written at step t-1)
            if (tid == 0) {
                const int* c = &g_cnt[g][t - 1];
                while (vloadi(c) < NRNK) { }
            }
            __syncthreads();
            __threadfence();  // acquire: order + invalidate L1 before re-reading g_H
            const float* src = &g_H[(t - 1) & 1][g * BB][0];
            for (int i = tid; i < BB * HH; i += 256)
                (&h_sm[0][0])[i] = vloadf(src + i);
        }
        __syncthreads();

        // ---- GEMM: zp[kh][b][n] = partial(bias + x@W_ih^T + h@W_hh^T) ----
        #pragma unroll 1
        for (int b = 0; b < BB; b++) {
            float a0 = (kh == 0) ? bias : 0.0f, a1 = 0.0f, a2 = 0.0f, a3 = 0.0f;
            const float* hr = &h_sm[b][kh * 128];
            #pragma unroll
            for (int kk = 0; kk < 128; kk += 4) {
                float4 v = *(const float4*)(hr + kk);
                a0 = fmaf(Wr[kk + 0], v.x, a0);
                a1 = fmaf(Wr[kk + 1], v.y, a1);
                a2 = fmaf(Wr[kk + 2], v.z, a2);
                a3 = fmaf(Wr[kk + 3], v.w, a3);
            }
            const float* xr = &x_sm[b][kh * 32];
            #pragma unroll
            for (int dd = 0; dd < 32; dd += 4) {
                float4 v = *(const float4*)(xr + dd);
                a0 = fmaf(Wi[dd + 0], v.x, a0);
                a1 = fmaf(Wi[dd + 1], v.y, a1);
                a2 = fmaf(Wi[dd + 2], v.z, a2);
                a3 = fmaf(Wi[dd + 3], v.w, a3);
            }
            zp[kh][b][n] = (a0 + a1) + (a2 + a3);
        }
        __syncthreads();

        // ---- cell update: 512 cells, 2 per thread ----
        for (int e = tid; e < BB * HU; e += 256) {
            int b = e >> 5, uu = e & 31;
            float zi = zp[0][b][uu]      + zp[1][b][uu];
            float zf = zp[0][b][32 + uu] + zp[1][b][32 + uu];
            float zg = zp[0][b][64 + uu] + zp[1][b][64 + uu];
            float zo = zp[0][b][96 + uu] + zp[1][b][96 + uu];
            float si = 1.0f / (1.0f + __expf(-zi));
            float sf = 1.0f / (1.0f + __expf(-zf));
            float so = 1.0f / (1.0f + __expf(-zo));
            float c  = sf * c_sm[e] + si * tanhf(zg);
            c_sm[e]  = c;
            g_H[t & 1][g * BB + b][r * HU + uu] = so * tanhf(c);
        }
        __threadfence();   // release: h slice visible device-wide before signal
        __syncthreads();
        if (tid == 0) atomicAdd(&g_cnt[g][t], 1);
    }

    // ---- final head: rank 0 of each group computes sigmoid(hT @ W_out^T + b_out) ----
    if (r == 0) {
        if (tid == 0) {
            const int* c = &g_cnt[g][TT - 1];
            while (vloadi(c) < NRNK) { }
        }
        __syncthreads();
        __threadfence();
        const float* src = &g_H[(TT - 1) & 1][g * BB][0];
        for (int i = tid; i < BB * HH; i += 256)
            (&h_sm[0][0])[i] = vloadf(src + i);
        __syncthreads();
        if (tid < BB * 10) {
            int b = tid / 10, c = tid % 10;
            float acc = b_out[c];
            #pragma unroll 4
            for (int k = 0; k < HH; k++)
                acc = fmaf(h_sm[b][k], W_out[c * HH + k], acc);
            out[(g * BB + b) * 10 + c] = 1.0f / (1.0f + __expf(-acc));
        }
    }

    // ---- reset counters so the next graph replay starts clean ----
    __syncthreads();
    if (tid == 0) {
        __threadfence();
        atomicAdd(&g_done[g], 1);
        if (r == 0) {
            const int* dptr = &g_done[g];
            while (vloadi(dptr) < NRNK) { }
            for (int t = 0; t < TT; t++) g_cnt[g][t] = 0;
            __threadfence();
            g_done[g] = 0;
            __threadfence();
        }
    }
}

extern "C" void kernel_launch(void* const* d_in, const int* in_sizes, int n_in,
                              void* d_out, int out_size)
{
    (void)in_sizes; (void)n_in; (void)out_size;
    const float* x     = (const float*)d_in[0];
    const float* W_ih  = (const float*)d_in[1];
    const float* W_hh  = (const float*)d_in[2];
    const float* b_ih  = (const float*)d_in[3];
    const float* b_hh  = (const float*)d_in[4];
    const float* W_out = (const float*)d_in[5];
    const float* b_out = (const float*)d_in[6];
    float* out = (float*)d_out;

    lstm_persistent_kernel<<<NGRP * NRNK, 256>>>(x, W_ih, W_hh, b_ih, b_hh,
                                                 W_out, b_out, out);
}

// round 2
// speedup vs baseline: 1.1873x; 1.1873x over previous
#include <cuda_runtime.h>

// LSTM_10960756539796: B=256, T=512, D=64, H=256, C=10
// Persistent kernel, 128 CTAs x 512 threads.
//   group g = blockIdx/8 -> batch rows [g*16, g*16+16)
//   rank  r = blockIdx%8 -> hidden units [r*32, r*32+32) (128 gate rows)
// Within CTA: n = tid&127 gate row, kq = tid>>7 k-quarter (64 k's, 16 d's).
// W_hh slice register-resident, packed along k as u64 pairs for fma.rn.f32x2.

#define BATCH 256
#define TT    512
#define DD    64
#define HH    256
#define NGRP  16
#define NRNK  8
#define BB    16
#define HU    32
#define NL    128
#define NTHR  512

typedef unsigned long long u64;

__device__ float g_H[2][BATCH][HH];
__device__ int   g_cnt[NGRP][TT];
__device__ int   g_done[NGRP];

__device__ __forceinline__ int   vloadi(const int* p)   { return *(const volatile int*)p; }
__device__ __forceinline__ float vloadf(const float* p) { return *(const volatile float*)p; }

__device__ __forceinline__ u64 fma2(u64 a, u64 b, u64 c) {
    u64 d;
    asm("fma.rn.f32x2 %0, %1, %2, %3;" : "=l"(d) : "l"(a), "l"(b), "l"(c));
    return d;
}
__device__ __forceinline__ float hsum2(u64 v) {
    float lo, hi;
    asm("mov.b64 {%0,%1}, %2;" : "=f"(lo), "=f"(hi) : "l"(v));
    return lo + hi;
}

__global__ __launch_bounds__(NTHR, 1)
void lstm_persistent_kernel(const float* __restrict__ x,
                            const float* __restrict__ W_ih,
                            const float* __restrict__ W_hh,
                            const float* __restrict__ b_ih,
                            const float* __restrict__ b_hh,
                            const float* __restrict__ W_out,
                            const float* __restrict__ b_out,
                            float* __restrict__ out)
{
    extern __shared__ __align__(16) char smem_raw[];
    float (*h_sm)[HH]     = (float (*)[HH])(smem_raw);                 // 16 KB
    float (*x_sm)[DD]     = (float (*)[DD])(smem_raw + 16384);         //  4 KB
    float (*zp)[BB][NL]   = (float (*)[BB][NL])(smem_raw + 20480);     // 32 KB

    const int g   = blockIdx.x >> 3;
    const int r   = blockIdx.x & 7;
    const int tid = threadIdx.x;
    const int n   = tid & 127;          // gate row (gate*32 + u)
    const int kq  = tid >> 7;           // k-quarter 0..3
    const int gate  = n >> 5;
    const int u     = n & 31;
    const int nglob = gate * HH + r * HU + u;

    // ---- register-resident weights, packed along k (u64 = {w[2i], w[2i+1]}) ----
    u64 W2[32];
    {
        const u64* wp = (const u64*)(W_hh + (size_t)nglob * HH + kq * 64);
        #pragma unroll
        for (int i = 0; i < 32; i++) W2[i] = wp[i];
    }
    u64 Wi2[8];
    {
        const u64* wp = (const u64*)(W_ih + (size_t)nglob * DD + kq * 16);
        #pragma unroll
        for (int i = 0; i < 8; i++) Wi2[i] = wp[i];
    }
    const float bias = b_ih[nglob] + b_hh[nglob];   // applied only by kq==0

    // cell state lives in a register: thread tid owns cell (b=tid>>5, u=tid&31)
    const int cb = tid >> 5;
    const int cu = tid & 31;
    float creg = 0.0f;

    for (int i = tid; i < BB * HH; i += NTHR) (&h_sm[0][0])[i] = 0.0f;
    __syncthreads();

    const float* xbase = x + (size_t)(g * BB) * TT * DD;

    #pragma unroll 1
    for (int t = 0; t < TT; t++) {
        // x_t tile: 1024 floats
        for (int i = tid; i < BB * DD; i += NTHR) {
            int b = i >> 6, d = i & 63;
            x_sm[b][d] = xbase[((size_t)b * TT + t) * DD + d];
        }
        if (t > 0) {
            if (tid == 0) {
                const int* c = &g_cnt[g][t - 1];
                while (vloadi(c) < NRNK) { }
            }
            __syncthreads();
            __threadfence();
            const float* src = &g_H[(t - 1) & 1][g * BB][0];
            for (int i = tid; i < BB * HH; i += NTHR)
                (&h_sm[0][0])[i] = vloadf(src + i);
        }
        __syncthreads();

        // ---- GEMM partials: zp[kq][b][n] ----
        #pragma unroll 1
        for (int b = 0; b < BB; b++) {
            u64 a0 = 0, a1 = 0, a2 = 0, a3 = 0;
            const ulonglong2* hp = (const ulonglong2*)(&h_sm[b][kq * 64]);
            #pragma unroll
            for (int i = 0; i < 16; i += 2) {
                ulonglong2 v = hp[i];
                ulonglong2 w = hp[i + 1];
                a0 = fma2(W2[2 * i + 0], v.x, a0);
                a1 = fma2(W2[2 * i + 1], v.y, a1);
                a2 = fma2(W2[2 * i + 2], w.x, a2);
                a3 = fma2(W2[2 * i + 3], w.y, a3);
            }
            const ulonglong2* xp = (const ulonglong2*)(&x_sm[b][kq * 16]);
            #pragma unroll
            for (int i = 0; i < 4; i += 2) {
                ulonglong2 v = xp[i];
                ulonglong2 w = xp[i + 1];
                a0 = fma2(Wi2[2 * i + 0], v.x, a0);
                a1 = fma2(Wi2[2 * i + 1], v.y, a1);
                a2 = fma2(Wi2[2 * i + 2], w.x, a2);
                a3 = fma2(Wi2[2 * i + 3], w.y, a3);
            }
            float s = (hsum2(a0) + hsum2(a1)) + (hsum2(a2) + hsum2(a3));
            if (kq == 0) s += bias;
            zp[kq][b][n] = s;
        }
        __syncthreads();

        // ---- cell update: exactly 1 cell per thread ----
        {
            float zi = (zp[0][cb][cu]      + zp[1][cb][cu])      + (zp[2][cb][cu]      + zp[3][cb][cu]);
            float zf = (zp[0][cb][32 + cu] + zp[1][cb][32 + cu]) + (zp[2][cb][32 + cu] + zp[3][cb][32 + cu]);
            float zg = (zp[0][cb][64 + cu] + zp[1][cb][64 + cu]) + (zp[2][cb][64 + cu] + zp[3][cb][64 + cu]);
            float zo = (zp[0][cb][96 + cu] + zp[1][cb][96 + cu]) + (zp[2][cb][96 + cu] + zp[3][cb][96 + cu]);
            float si = 1.0f / (1.0f + __expf(-zi));
            float sf = 1.0f / (1.0f + __expf(-zf));
            float so = 1.0f / (1.0f + __expf(-zo));
            creg = sf * creg + si * tanhf(zg);
            g_H[t & 1][g * BB + cb][r * HU + cu] = so * tanhf(creg);
        }
        __threadfence();
        __syncthreads();
        if (tid == 0) atomicAdd(&g_cnt[g][t], 1);
    }

    // ---- head: rank 0 per group ----
    if (r == 0) {
        if (tid == 0) {
            const int* c = &g_cnt[g][TT - 1];
            while (vloadi(c) < NRNK) { }
        }
        __syncthreads();
        __threadfence();
        const float* src = &g_H[(TT - 1) & 1][g * BB][0];
        for (int i = tid; i < BB * HH; i += NTHR)
            (&h_sm[0][0])[i] = vloadf(src + i);
        __syncthreads();
        if (tid < BB * 10) {
            int b = tid / 10, c = tid % 10;
            float acc = b_out[c];
            #pragma unroll 4
            for (int k = 0; k < HH; k++)
                acc = fmaf(h_sm[b][k], W_out[c * HH + k], acc);
            out[(g * BB + b) * 10 + c] = 1.0f / (1.0f + __expf(-acc));
        }
    }

    // ---- reset counters for next graph replay ----
    __syncthreads();
    if (tid == 0) {
        __threadfence();
        atomicAdd(&g_done[g], 1);
        if (r == 0) {
            const int* dptr = &g_done[g];
            while (vloadi(dptr) < NRNK) { }
            for (int t = 0; t < TT; t++) g_cnt[g][t] = 0;
            __threadfence();
            g_done[g] = 0;
            __threadfence();
        }
    }
}

extern "C" void kernel_launch(void* const* d_in, const int* in_sizes, int n_in,
                              void* d_out, int out_size)
{
    (void)in_sizes; (void)n_in; (void)out_size;
    const float* x     = (const float*)d_in[0];
    const float* W_ih  = (const float*)d_in[1];
    const float* W_hh  = (const float*)d_in[2];
    const float* b_ih  = (const float*)d_in[3];
    const float* b_hh  = (const float*)d_in[4];
    const float* W_out = (const float*)d_in[5];
    const float* b_out = (const float*)d_in[6];
    float* outp = (float*)d_out;

    const int smem_bytes = 16384 + 4096 + 32768;   // 52 KB
    cudaFuncSetAttribute(lstm_persistent_kernel,
                         cudaFuncAttributeMaxDynamicSharedMemorySize, smem_bytes);
    lstm_persistent_kernel<<<NGRP * NRNK, NTHR, smem_bytes>>>(
        x, W_ih, W_hh, b_ih, b_hh, W_out, b_out, outp);
}